// round 7
// baseline (speedup 1.0000x reference)
#include <cuda_runtime.h>
#include <math.h>

#define BATCH   16384
#define CCH     72
#define HH      34
#define SAMP    (CCH*HH)      /* 2448 */
#define OUTC    84
#define OSAMP   (OUTC*HH)     /* 2856 */
#define TB      8             /* samples per conv block */
#define BT      288           /* conv block threads = TB*36 */
#define RED_BLOCKS 64
#define RED_PER    256
#define BN_COUNT   (16384.0f*34.0f)
#define BN_EPS_F   1e-5f

__device__ float g_mult[BATCH*6];
__device__ float g_part[BATCH*144];
__device__ float g_part2[RED_BLOCKS*144];
__device__ float g_ss[144];

__device__ __forceinline__ float sigmoidf_(float z) {
    return 1.0f / (1.0f + __expf(-z));
}

#define FMA2(d, a, b, c) \
    asm("fma.rn.f32x2 %0, %1, %2, %3;" : "=l"(d) : "l"(a), "l"(b), "l"(c))
#define ADD2(d, a, b) \
    asm("add.rn.f32x2 %0, %1, %2;" : "=l"(d) : "l"(a), "l"(b))
#define PACK2(p, v) do { unsigned int _b = __float_as_uint(v); \
    asm("mov.b64 %0, {%1, %1};" : "=l"(p) : "r"(_b)); } while (0)
#define UNPACK2(lo, hi, p) do { unsigned int _l, _h; \
    asm("mov.b64 {%0, %1}, %2;" : "=r"(_l), "=r"(_h) : "l"(p)); \
    lo = __uint_as_float(_l); hi = __uint_as_float(_h); } while (0)

// ---------------------------------------------------------------------------
// K1: per-sample gates + BN partial sums + copy x into output channels [0,72)
// ---------------------------------------------------------------------------
__global__ void __launch_bounds__(128) k1_stats(
    const float* __restrict__ x,
    const float* __restrict__ fcw,
    const float* __restrict__ fcb,
    float* __restrict__ out)
{
    __shared__ float xs[SAMP];
    __shared__ float ws[HH];
    __shared__ float s1[CCH], s2[CCH], sw[CCH];
    __shared__ float lin[6];

    const int b   = blockIdx.x;
    const int tid = threadIdx.x;

    const float4* xin4 = (const float4*)(x + (size_t)b * SAMP);
    float4*       out4 = (float4*)(out + (size_t)b * OSAMP);
    float4*       xs4  = (float4*)xs;
    #pragma unroll
    for (int i = tid; i < SAMP/4; i += 128) {
        float4 v = xin4[i];
        xs4[i]  = v;
        out4[i] = v;
    }
    if (tid < HH) ws[tid] = fcw[tid];
    __syncthreads();

    if (tid < CCH) {
        float a1 = 0.f, a2 = 0.f, aw = 0.f;
        const float* row = xs + tid * HH;
        #pragma unroll
        for (int h = 0; h < HH; h++) {
            float v = row[h];
            a1 += v; a2 += v * v; aw += v * ws[h];
        }
        s1[tid] = a1; s2[tid] = a2; sw[tid] = aw;
    }
    __syncthreads();

    if (tid < 6) {
        float s = 0.f;
        #pragma unroll
        for (int c = 0; c < 12; c++) s += sw[tid * 12 + c];
        lin[tid] = s * (1.0f/12.0f) + fcb[0];
    }
    __syncthreads();

    if (tid < CCH) {
        const int cls = tid / 12;
        float mult;
        if (cls == 0)       mult = sigmoidf_(lin[5] + lin[0]);
        else if (cls == 5)  mult = 1.0f;
        else                mult = sigmoidf_(lin[5 - cls] + lin[5]);
        int src;
        if (cls == 0 || cls == 5) src = tid;
        else                      src = tid + 12 * (5 - 2 * cls);

        g_part[(size_t)b * 144 + tid * 2 + 0] = mult * s1[src];
        g_part[(size_t)b * 144 + tid * 2 + 1] = mult * mult * s2[src];
        if ((tid % 12) == 0) g_mult[b * 6 + cls] = mult;
    }
}

// ---------------------------------------------------------------------------
// K2 / K2b: deterministic BN stat reduction
// ---------------------------------------------------------------------------
__global__ void __launch_bounds__(144) k2_reduce()
{
    const int t   = threadIdx.x;
    const int blk = blockIdx.x;
    float acc = 0.f;
    size_t base = (size_t)blk * RED_PER * 144 + t;
    #pragma unroll 8
    for (int i = 0; i < RED_PER; i++) acc += g_part[base + (size_t)i * 144];
    g_part2[blk * 144 + t] = acc;
}

__global__ void __launch_bounds__(72) k2b_final(
    const float* __restrict__ gamma,
    const float* __restrict__ beta)
{
    const int c = threadIdx.x;
    float s = 0.f, q = 0.f;
    #pragma unroll 8
    for (int i = 0; i < RED_BLOCKS; i++) {
        s += g_part2[i * 144 + 2 * c + 0];
        q += g_part2[i * 144 + 2 * c + 1];
    }
    const float inv = 1.0f / BN_COUNT;
    float mu    = s * inv;
    float var   = q * inv - mu * mu;
    float scale = gamma[c] * rsqrtf(var + BN_EPS_F);
    g_ss[c]      = scale;
    g_ss[72 + c] = beta[c] - mu * scale;
}

// ---------------------------------------------------------------------------
// K3: xxx -> BN -> relu (fp32 smem) -> 3-tap conv
// 288 threads: build = 8 samples x 36 slots; conv = 8 x 9 h-quads x 4 ic-quarters
// FFMA2 over oc-pairs, 4 h per thread, ic split 4-way, butterfly combine
// ---------------------------------------------------------------------------
__global__ void __launch_bounds__(BT, 2) k3_conv(
    const float* __restrict__ x,
    const float* __restrict__ convw,
    float* __restrict__ out)
{
    extern __shared__ float sm[];
    float* wsm  = sm;                    // 2592 weights [(ic*3+k)*12 + oc]
    float* hp   = wsm + 2592;            // TB*2592 padded relu'd xxx (xxx-chan order)
    float* Asl  = hp  + TB * 2592;       // TB*72 combined scale
    float* Bc   = Asl + TB * 72;         // 72 shift
    int*   offc = (int*)(Bc + 72);       // 72 dst offset (xc*36)
    float* scx  = (float*)(offc + 72);   // 72
    float* mlsh = scx + 72;              // TB*6

    const int tid = threadIdx.x;
    const int b0  = blockIdx.x * TB;

    // weights -> smem
    for (int i = tid; i < 2592; i += BT) {
        int oc = i % 12;
        int k  = (i / 12) % 3;
        int ic = i / 36;
        wsm[i] = convw[oc * 216 + ic * 3 + k];
    }
    if (tid < 72) {
        int g = tid / 12, r = tid - g * 12;
        int xcls = (g == 0 || g == 5) ? g : (5 - g);
        int xc   = 12 * xcls + r;
        scx[tid]  = g_ss[xc];
        Bc[tid]   = g_ss[72 + xc];
        offc[tid] = xc * 36;
    }
    if (tid < TB * 6) mlsh[tid] = g_mult[b0 * 6 + tid];
    __syncthreads();

    for (int i = tid; i < TB * 72; i += BT) {
        int s = i / 72;
        int c = i - s * 72;
        int g = c / 12;
        int xcls = (g == 0 || g == 5) ? g : (5 - g);
        Asl[i] = scx[c] * mlsh[s * 6 + xcls];
    }
    __syncthreads();

    // hp build: thread owns (sample sb, slot m in 0..35); pads written inline
    {
        const int sb = tid / 36;
        const int m  = tid - sb * 36;
        const bool interior = (m >= 1) && (m <= 34);
        const float* xr = x + (size_t)(b0 + sb) * SAMP + (m - 1);
        const float* As = Asl + sb * 72;
        float*       hb = hp + sb * 2592 + m;
        #pragma unroll 8
        for (int c = 0; c < 72; c++) {
            float hv = 0.f;
            if (interior) {
                float v = xr[c * HH];
                hv = fmaxf(fmaf(As[c], v, Bc[c]), 0.f);
            }
            hb[offc[c]] = hv;
        }
    }
    __syncthreads();

    // conv: thread = (s, q, e); h outputs 4q..4q+3; ic in [18e, 18e+18)
    {
        const int e = tid & 3;
        const int q = (tid >> 2) % 9;
        const int s = tid / 36;
        const bool full = (q < 8);

        unsigned long long acc[6][4];
        #pragma unroll
        for (int p = 0; p < 6; p++)
            #pragma unroll
            for (int d = 0; d < 4; d++) acc[p][d] = 0ULL;

        const float*      hrow = hp + s * 2592 + e * (18 * 36) + 4 * q;
        const ulonglong2* w16  = (const ulonglong2*)wsm + e * (18 * 9);

        #pragma unroll 3
        for (int ic = 0; ic < 18; ic++) {
            const float* hb = hrow + ic * 36;
            float2 p01 = *(const float2*)(hb);
            float2 p23 = *(const float2*)(hb + 2);
            float2 p45 = make_float2(0.f, 0.f);
            if (full) p45 = *(const float2*)(hb + 4);
            unsigned long long vp[6];
            PACK2(vp[0], p01.x);
            PACK2(vp[1], p01.y);
            PACK2(vp[2], p23.x);
            PACK2(vp[3], p23.y);
            PACK2(vp[4], p45.x);
            PACK2(vp[5], p45.y);
            const ulonglong2* wr = w16 + ic * 9;
            #pragma unroll
            for (int t = 0; t < 9; t++) {
                ulonglong2 ww = wr[t];
                const int k  = t / 3;        // tap
                const int pq = t % 3;        // oc quad
                #pragma unroll
                for (int d = 0; d < 4; d++) {
                    FMA2(acc[2*pq][d],     ww.x, vp[d + k], acc[2*pq][d]);
                    FMA2(acc[2*pq + 1][d], ww.y, vp[d + k], acc[2*pq + 1][d]);
                }
            }
        }

        // butterfly combine across the 4 ic-quarters (lanes e = lane&3)
        #pragma unroll
        for (int p = 0; p < 6; p++) {
            #pragma unroll
            for (int d = 0; d < 4; d++) {
                unsigned long long v = acc[p][d];
                unsigned long long r1 = __shfl_xor_sync(0xFFFFFFFFu, v, 1);
                ADD2(v, v, r1);
                unsigned long long r2 = __shfl_xor_sync(0xFFFFFFFFu, v, 2);
                ADD2(v, v, r2);
                acc[p][d] = v;
            }
        }

        // lane e stores h = 4q + e (if valid)
        const int h = 4 * q + e;
        if (h < HH) {
            float* ob = out + (size_t)(b0 + s) * OSAMP + 72 * HH + h;
            #pragma unroll
            for (int p = 0; p < 6; p++) {
                float lo, hi;
                UNPACK2(lo, hi, acc[p][e]);
                ob[(2*p)     * HH] = lo;
                ob[(2*p + 1) * HH] = hi;
            }
        }
    }
}

// ---------------------------------------------------------------------------
extern "C" void kernel_launch(void* const* d_in, const int* in_sizes, int n_in,
                              void* d_out, int out_size)
{
    const float* x      = (const float*)d_in[0];
    const float* gamma  = (const float*)d_in[1];
    const float* beta   = (const float*)d_in[2];
    const float* conv_w = (const float*)d_in[3];
    const float* fc_w   = (const float*)d_in[4];
    const float* fc_b   = (const float*)d_in[5];
    float* out = (float*)d_out;

    const int B = in_sizes[0] / SAMP;   // 16384

    const int smem_k3 = 10368 + TB*2592*4 + TB*72*4 + 288 + 288 + 288 + TB*6*4; // 96672
    cudaFuncSetAttribute(k3_conv, cudaFuncAttributeMaxDynamicSharedMemorySize, smem_k3);

    k1_stats<<<B, 128>>>(x, fc_w, fc_b, out);
    k2_reduce<<<RED_BLOCKS, 144>>>();
    k2b_final<<<1, 72>>>(gamma, beta);
    k3_conv<<<B / TB, BT, smem_k3>>>(x, conv_w, out);
}

// round 9
// speedup vs baseline: 1.3847x; 1.3847x over previous
#include <cuda_runtime.h>
#include <cuda_bf16.h>
#include <math.h>
#include <cstdint>

#define BATCH   16384
#define CCH     72
#define HH      34
#define SAMP    2448
#define OSAMP   2856
#define TB      8             /* samples per conv block */
#define BT      288           /* conv block threads (9 warps, 18 m16-tiles) */
#define RED_BLOCKS 64
#define RED_PER    256
#define BN_COUNT   (16384.0f*34.0f)
#define BN_EPS_F   1e-5f

/* k3 smem layout (bytes) */
#define OFF_ASL 0             /* 576 f  */
#define OFF_BC  2304          /* 72 f   */
#define OFF_SCX 2592          /* 72 f   */
#define OFF_XC  2880          /* 72 i   */
#define OFF_ML  3168          /* 48 f   */
#define OFF_A   3584          /* 18*9*32*16 = 82944 */
#define OFF_B   86528         /* 6912*4 = 27648 */
#define SMEM_K3 114176
#define OFF_D   OFF_A         /* D overlays A: 288 x 50 f = 57600 */
#define DSTRIDE 50

__device__ float g_mult[BATCH*6];
__device__ float g_part[BATCH*144];
__device__ float g_part2[RED_BLOCKS*144];
__device__ float g_ss[144];
__device__ unsigned int g_Bf[6912];   /* B fragments: [(nt*9+ks)*2+ch][lane][2] */

__device__ __forceinline__ float sigmoidf_(float z) {
    return 1.0f / (1.0f + __expf(-z));
}

#define MMA16816(d, a, bx, by) \
    asm volatile("mma.sync.aligned.m16n8k16.row.col.f32.bf16.bf16.f32 " \
        "{%0,%1,%2,%3}, {%4,%5,%6,%7}, {%8,%9}, {%0,%1,%2,%3};" \
        : "+f"((d)[0]), "+f"((d)[1]), "+f"((d)[2]), "+f"((d)[3]) \
        : "r"((a).x), "r"((a).y), "r"((a).z), "r"((a).w), "r"(bx), "r"(by))

// ---------------------------------------------------------------------------
// K1: per-sample gates + BN partial sums + copy x into output channels [0,72)
// ---------------------------------------------------------------------------
__global__ void __launch_bounds__(128) k1_stats(
    const float* __restrict__ x, const float* __restrict__ fcw,
    const float* __restrict__ fcb, float* __restrict__ out)
{
    __shared__ float xs[SAMP];
    __shared__ float ws[HH];
    __shared__ float s1[CCH], s2[CCH], sw[CCH];
    __shared__ float lin[6];

    const int b = blockIdx.x, tid = threadIdx.x;
    const float4* xin4 = (const float4*)(x + (size_t)b * SAMP);
    float4* out4 = (float4*)(out + (size_t)b * OSAMP);
    float4* xs4 = (float4*)xs;
    #pragma unroll
    for (int i = tid; i < SAMP/4; i += 128) { float4 v = xin4[i]; xs4[i] = v; out4[i] = v; }
    if (tid < HH) ws[tid] = fcw[tid];
    __syncthreads();

    if (tid < CCH) {
        float a1 = 0.f, a2 = 0.f, aw = 0.f;
        const float* row = xs + tid * HH;
        #pragma unroll
        for (int h = 0; h < HH; h++) { float v = row[h]; a1 += v; a2 += v*v; aw += v*ws[h]; }
        s1[tid] = a1; s2[tid] = a2; sw[tid] = aw;
    }
    __syncthreads();
    if (tid < 6) {
        float s = 0.f;
        #pragma unroll
        for (int c = 0; c < 12; c++) s += sw[tid*12 + c];
        lin[tid] = s * (1.0f/12.0f) + fcb[0];
    }
    __syncthreads();
    if (tid < CCH) {
        const int cls = tid / 12;
        float mult;
        if (cls == 0)      mult = sigmoidf_(lin[5] + lin[0]);
        else if (cls == 5) mult = 1.0f;
        else               mult = sigmoidf_(lin[5-cls] + lin[5]);
        int src = (cls == 0 || cls == 5) ? tid : tid + 12*(5 - 2*cls);
        g_part[(size_t)b*144 + tid*2 + 0] = mult * s1[src];
        g_part[(size_t)b*144 + tid*2 + 1] = mult * mult * s2[src];
        if ((tid % 12) == 0) g_mult[b*6 + cls] = mult;
    }
}

__global__ void __launch_bounds__(144) k2_reduce()
{
    const int t = threadIdx.x, blk = blockIdx.x;
    float acc = 0.f;
    size_t base = (size_t)blk * RED_PER * 144 + t;
    #pragma unroll 8
    for (int i = 0; i < RED_PER; i++) acc += g_part[base + (size_t)i * 144];
    g_part2[blk*144 + t] = acc;
}

__global__ void __launch_bounds__(72) k2b_final(
    const float* __restrict__ gamma, const float* __restrict__ beta)
{
    const int c = threadIdx.x;
    float s = 0.f, q = 0.f;
    #pragma unroll 8
    for (int i = 0; i < RED_BLOCKS; i++) {
        s += g_part2[i*144 + 2*c + 0];
        q += g_part2[i*144 + 2*c + 1];
    }
    const float inv = 1.0f / BN_COUNT;
    float mu = s*inv, var = q*inv - mu*mu;
    float scale = gamma[c] * rsqrtf(var + BN_EPS_F);
    g_ss[c] = scale;
    g_ss[72+c] = beta[c] - mu*scale;
}

// ---------------------------------------------------------------------------
// K2c: build B fragments (bf16 hi/lo chains) in mma.sync col-major layout.
// N = 48 = 3 taps x 16 (oc 0..11 used); K pair p in ks -> channel ks*8+p.
// chain0 unit = (wh, wh); chain1 unit = (wl, 0).
// ---------------------------------------------------------------------------
__global__ void __launch_bounds__(256) k2c_wb(const float* __restrict__ convw)
{
    for (int idx = threadIdx.x; idx < 6912; idx += 256) {
        int r  = idx & 1;
        int l  = (idx >> 1) & 31;
        int q  = idx >> 6;
        int ch = q & 1;
        int q2 = q >> 1;
        int ks = q2 % 9;
        int nt = q2 / 9;
        int n   = nt*8 + (l >> 2);
        int tap = n >> 4;
        int oc  = n & 15;
        int chan = ks*8 + (l & 3) + 4*r;
        unsigned int val = 0u;
        if (oc < 12) {
            float w = convw[oc*216 + chan*3 + tap];
            __nv_bfloat16 hb = __float2bfloat16(w);
            if (ch == 0) {
                unsigned int u = (unsigned int)__bfloat16_as_ushort(hb);
                val = u | (u << 16);
            } else {
                float wl = w - __bfloat162float(hb);
                val = (unsigned int)__bfloat16_as_ushort(__float2bfloat16(wl));
            }
        }
        g_Bf[idx] = val;
    }
}

// ---------------------------------------------------------------------------
// K3: BN/relu -> bf16 hi/lo A fragments in smem -> mma.sync GEMM -> tap epilogue
// ---------------------------------------------------------------------------
__global__ void __launch_bounds__(BT, 2) k3_mma(
    const float* __restrict__ x, float* __restrict__ out)
{
    extern __shared__ char smem[];
    float*        Asl  = (float*)(smem + OFF_ASL);
    float*        Bc   = (float*)(smem + OFF_BC);
    float*        scx  = (float*)(smem + OFF_SCX);
    int*          cpart= (int*)  (smem + OFF_XC);
    float*        mlsh = (float*)(smem + OFF_ML);
    unsigned int* Amem = (unsigned int*)(smem + OFF_A);
    unsigned int* Bmem = (unsigned int*)(smem + OFF_B);
    float*        Dmem = (float*)(smem + OFF_D);

    const int tid  = threadIdx.x;
    const int wid  = tid >> 5;
    const int lane = tid & 31;
    const int b0   = blockIdx.x * TB;

    // tables
    if (tid < 72) {
        int g = tid/12, r = tid - g*12;
        int xcls = (g == 0 || g == 5) ? g : (5 - g);
        int xc = 12*xcls + r;
        scx[tid] = g_ss[xc];
        Bc[tid]  = g_ss[72 + xc];
        /* channel-dependent u32 index: ks*128 + (u&3)*4 + (u>>2)*2, u = xc&7 */
        cpart[tid] = (xc >> 3)*128 + (xc & 3)*4 + 2*((xc & 7) >> 2);
    }
    if (tid < TB*6) mlsh[tid] = g_mult[b0*6 + tid];
    // B fragments -> smem
    {
        const float4* src = (const float4*)g_Bf;
        float4* dst = (float4*)Bmem;
        #pragma unroll
        for (int i = tid; i < 1728; i += BT) dst[i] = src[i];
    }
    __syncthreads();

    for (int i = tid; i < TB*72; i += BT) {
        int s = i / 72, c = i - s*72;
        int g = c / 12;
        int xcls = (g == 0 || g == 5) ? g : (5 - g);
        Asl[i] = scx[c] * mlsh[s*6 + xcls];
    }
    __syncthreads();

    // A build: thread = row (s*36 + m); pads m=0,35 are zero rows
    // u32 index = mt*1152 + g*16 + rowhalf + [ks*128 + (u&3)*4 + (u>>2)*2]
    {
        const int row = tid;
        const int s = row / 36;
        const int m = row - s*36;
        const bool interior = (m >= 1) && (m <= 34);
        const float* xr = x + (size_t)(b0 + s) * SAMP + (m - 1);
        const float* As = Asl + s*72;
        const int rowin = row & 15;
        const int rpart = (row >> 4)*1152 + (rowin & 7)*16 + (rowin >> 3);
        #pragma unroll 4
        for (int c = 0; c < 72; c++) {
            float hv = 0.f;
            if (interior) hv = fmaxf(fmaf(As[c], xr[c*HH], Bc[c]), 0.f);
            __nv_bfloat16 hb = __float2bfloat16(hv);
            float lof = hv - __bfloat162float(hb);
            unsigned int u = (unsigned int)__bfloat16_as_ushort(hb)
                | ((unsigned int)__bfloat16_as_ushort(__float2bfloat16(lof)) << 16);
            Amem[rpart + cpart[c]] = u;
        }
    }
    __syncthreads();

    // mainloop: warp owns m-tiles 2*wid, 2*wid+1
    float d[2][6][4];
    #pragma unroll
    for (int i = 0; i < 2; i++)
        #pragma unroll
        for (int n = 0; n < 6; n++)
            #pragma unroll
            for (int r = 0; r < 4; r++) d[i][n][r] = 0.f;

    {
        const int mt0 = wid*2, mt1 = wid*2 + 1;
        const uint4* Af = (const uint4*)Amem;
        const uint2* Bf = (const uint2*)Bmem;
        #pragma unroll
        for (int ks = 0; ks < 9; ks++) {
            uint4 a0 = Af[(mt0*9 + ks)*32 + lane];
            uint4 a1 = Af[(mt1*9 + ks)*32 + lane];
            #pragma unroll
            for (int nt = 0; nt < 6; nt++) {
                uint2 bh = Bf[((nt*9 + ks)*2 + 0)*32 + lane];
                uint2 bl = Bf[((nt*9 + ks)*2 + 1)*32 + lane];
                MMA16816(d[0][nt], a0, bh.x, bh.y);
                MMA16816(d[0][nt], a0, bl.x, bl.y);
                MMA16816(d[1][nt], a1, bh.x, bh.y);
                MMA16816(d[1][nt], a1, bl.x, bl.y);
            }
        }
    }
    __syncthreads();   // all A reads done; D overlays A

    // store D to smem: row-major, stride 50
    {
        #pragma unroll
        for (int i = 0; i < 2; i++) {
            const int row0 = (wid*2 + i)*16 + (lane >> 2);
            #pragma unroll
            for (int nt = 0; nt < 6; nt++) {
                const int col = nt*8 + 2*(lane & 3);
                *(float2*)(Dmem + row0*DSTRIDE + col)       = make_float2(d[i][nt][0], d[i][nt][1]);
                *(float2*)(Dmem + (row0 + 8)*DSTRIDE + col) = make_float2(d[i][nt][2], d[i][nt][3]);
            }
        }
    }
    __syncthreads();

    // epilogue: out[h,oc] = D[s36+h, oc] + D[s36+h+1, 16+oc] + D[s36+h+2, 32+oc]
    if (tid < 272) {
        const int s = tid / 34;
        const int h = tid - s*34;
        const float* dr = Dmem + (s*36 + h)*DSTRIDE;
        float* ob = out + (size_t)(b0 + s) * OSAMP + 72*HH + h;
        #pragma unroll
        for (int oc = 0; oc < 12; oc++) {
            float v = dr[oc] + dr[DSTRIDE + 16 + oc] + dr[2*DSTRIDE + 32 + oc];
            ob[oc*HH] = v;
        }
    }
}

// ---------------------------------------------------------------------------
extern "C" void kernel_launch(void* const* d_in, const int* in_sizes, int n_in,
                              void* d_out, int out_size)
{
    const float* x      = (const float*)d_in[0];
    const float* gamma  = (const float*)d_in[1];
    const float* beta   = (const float*)d_in[2];
    const float* conv_w = (const float*)d_in[3];
    const float* fc_w   = (const float*)d_in[4];
    const float* fc_b   = (const float*)d_in[5];
    float* out = (float*)d_out;

    const int B = in_sizes[0] / SAMP;   // 16384

    cudaFuncSetAttribute(k3_mma, cudaFuncAttributeMaxDynamicSharedMemorySize, SMEM_K3);

    k1_stats<<<B, 128>>>(x, fc_w, fc_b, out);
    k2_reduce<<<RED_BLOCKS, 144>>>();
    k2b_final<<<1, 72>>>(gamma, beta);
    k2c_wb<<<1, 256>>>(conv_w);
    k3_mma<<<B / TB, BT, SMEM_K3>>>(x, out);
}

// round 10
// speedup vs baseline: 1.5435x; 1.1147x over previous
#include <cuda_runtime.h>
#include <cuda_bf16.h>
#include <math.h>
#include <cstdint>

#define BATCH   16384
#define CCH     72
#define HH      34
#define SAMP    2448
#define OSAMP   2856
#define TB      8             /* samples per conv block */
#define BT      288           /* conv block threads (9 warps, 18 m16-tiles) */
#define RED_BLOCKS 64
#define RED_PER    256
#define BN_COUNT   (16384.0f*34.0f)
#define BN_EPS_F   1e-5f

/* k3 smem layout (bytes) */
#define OFF_ASL 0             /* 576 f  */
#define OFF_BC  2304          /* 72 f   */
#define OFF_SCX 2592          /* 72 f   */
#define OFF_XC  2880          /* 72 i   */
#define OFF_ML  3168          /* 48 f   */
#define OFF_A   3584          /* 18*9*128 u32 = 82944 B */
#define OFF_B   86528         /* 3456 u32 = 13824 B */
#define SMEM_K3 100352
#define OFF_D   OFF_A         /* D overlays A: 288 x 50 f */
#define DSTRIDE 50

__device__ float g_mult[BATCH*6];
__device__ float g_part[BATCH*144];
__device__ float g_part2[RED_BLOCKS*144];
__device__ float g_ss[144];
__device__ unsigned int g_Bf[3456];   /* tf32 B fragments */

__device__ __forceinline__ float sigmoidf_(float z) {
    return 1.0f / (1.0f + __expf(-z));
}
__device__ __forceinline__ unsigned int f2tf32(float v) {
    unsigned int u;
    asm("cvt.rna.tf32.f32 %0, %1;" : "=r"(u) : "f"(v));
    return u;
}

#define MMAT32(d, a, bx, by) \
    asm volatile("mma.sync.aligned.m16n8k8.row.col.f32.tf32.tf32.f32 " \
        "{%0,%1,%2,%3}, {%4,%5,%6,%7}, {%8,%9}, {%0,%1,%2,%3};" \
        : "+f"((d)[0]), "+f"((d)[1]), "+f"((d)[2]), "+f"((d)[3]) \
        : "r"((a).x), "r"((a).y), "r"((a).z), "r"((a).w), "r"(bx), "r"(by))

// ---------------------------------------------------------------------------
// K1: per-sample gates + BN partial sums + copy x into output channels [0,72)
// ---------------------------------------------------------------------------
__global__ void __launch_bounds__(128) k1_stats(
    const float* __restrict__ x, const float* __restrict__ fcw,
    const float* __restrict__ fcb, float* __restrict__ out)
{
    __shared__ float xs[SAMP];
    __shared__ float ws[HH];
    __shared__ float s1[CCH], s2[CCH], sw[CCH];
    __shared__ float lin[6];

    const int b = blockIdx.x, tid = threadIdx.x;
    const float4* xin4 = (const float4*)(x + (size_t)b * SAMP);
    float4* out4 = (float4*)(out + (size_t)b * OSAMP);
    float4* xs4 = (float4*)xs;
    #pragma unroll
    for (int i = tid; i < SAMP/4; i += 128) { float4 v = xin4[i]; xs4[i] = v; out4[i] = v; }
    if (tid < HH) ws[tid] = fcw[tid];
    __syncthreads();

    if (tid < CCH) {
        float a1 = 0.f, a2 = 0.f, aw = 0.f;
        const float* row = xs + tid * HH;
        #pragma unroll
        for (int h = 0; h < HH; h++) { float v = row[h]; a1 += v; a2 += v*v; aw += v*ws[h]; }
        s1[tid] = a1; s2[tid] = a2; sw[tid] = aw;
    }
    __syncthreads();
    if (tid < 6) {
        float s = 0.f;
        #pragma unroll
        for (int c = 0; c < 12; c++) s += sw[tid*12 + c];
        lin[tid] = s * (1.0f/12.0f) + fcb[0];
    }
    __syncthreads();
    if (tid < CCH) {
        const int cls = tid / 12;
        float mult;
        if (cls == 0)      mult = sigmoidf_(lin[5] + lin[0]);
        else if (cls == 5) mult = 1.0f;
        else               mult = sigmoidf_(lin[5-cls] + lin[5]);
        int src = (cls == 0 || cls == 5) ? tid : tid + 12*(5 - 2*cls);
        g_part[(size_t)b*144 + tid*2 + 0] = mult * s1[src];
        g_part[(size_t)b*144 + tid*2 + 1] = mult * mult * s2[src];
        if ((tid % 12) == 0) g_mult[b*6 + cls] = mult;
    }
}

__global__ void __launch_bounds__(144) k2_reduce()
{
    const int t = threadIdx.x, blk = blockIdx.x;
    float acc = 0.f;
    size_t base = (size_t)blk * RED_PER * 144 + t;
    #pragma unroll 8
    for (int i = 0; i < RED_PER; i++) acc += g_part[base + (size_t)i * 144];
    g_part2[blk*144 + t] = acc;
}

__global__ void __launch_bounds__(72) k2b_final(
    const float* __restrict__ gamma, const float* __restrict__ beta)
{
    const int c = threadIdx.x;
    float s = 0.f, q = 0.f;
    #pragma unroll 8
    for (int i = 0; i < RED_BLOCKS; i++) {
        s += g_part2[i*144 + 2*c + 0];
        q += g_part2[i*144 + 2*c + 1];
    }
    const float inv = 1.0f / BN_COUNT;
    float mu = s*inv, var = q*inv - mu*mu;
    float scale = gamma[c] * rsqrtf(var + BN_EPS_F);
    g_ss[c] = scale;
    g_ss[72+c] = beta[c] - mu*scale;
}

// ---------------------------------------------------------------------------
// K2c: build tf32 B fragments in mma.m16n8k8 col-major layout (parallel).
// N = 48 = 3 taps x 16 (oc 0..11 used); K = 72 channels = 9 ks x 8.
// u32 idx = ((nt*9+ks)*32 + lane)*2 + r;  k = (lane&3)+4r, col = lane>>2.
// ---------------------------------------------------------------------------
__global__ void __launch_bounds__(256) k2c_wb(const float* __restrict__ convw)
{
    int idx = blockIdx.x * 256 + threadIdx.x;
    if (idx >= 3456) return;
    int r  = idx & 1;
    int l  = (idx >> 1) & 31;
    int q  = idx >> 6;
    int ks = q % 9;
    int nt = q / 9;
    int n    = nt*8 + (l >> 2);
    int tap  = n >> 4;
    int oc   = n & 15;
    int chan = ks*8 + (l & 3) + 4*r;
    unsigned int val = 0u;
    if (oc < 12) val = f2tf32(convw[oc*216 + chan*3 + tap]);
    g_Bf[idx] = val;
}

// ---------------------------------------------------------------------------
// K3: BN/relu -> tf32 A fragments in smem -> mma.sync GEMM -> tap epilogue
// ---------------------------------------------------------------------------
__global__ void __launch_bounds__(BT, 2) k3_mma(
    const float* __restrict__ x, float* __restrict__ out)
{
    extern __shared__ char smem[];
    float*        Asl  = (float*)(smem + OFF_ASL);
    float*        Bc   = (float*)(smem + OFF_BC);
    float*        scx  = (float*)(smem + OFF_SCX);
    int*          cpart= (int*)  (smem + OFF_XC);
    float*        mlsh = (float*)(smem + OFF_ML);
    unsigned int* Amem = (unsigned int*)(smem + OFF_A);
    unsigned int* Bmem = (unsigned int*)(smem + OFF_B);
    float*        Dmem = (float*)(smem + OFF_D);

    const int tid  = threadIdx.x;
    const int wid  = tid >> 5;
    const int lane = tid & 31;
    const int b0   = blockIdx.x * TB;

    // tables
    if (tid < 72) {
        int g = tid/12, r = tid - g*12;
        int xcls = (g == 0 || g == 5) ? g : (5 - g);
        int xc = 12*xcls + r;
        scx[tid] = g_ss[xc];
        Bc[tid]  = g_ss[72 + xc];
        /* k = xc&7: idx-in-ks-block = (k&3)*4 + (k>>2)*2; plus ks*128 */
        cpart[tid] = (xc >> 3)*128 + (xc & 3)*4 + 2*((xc & 7) >> 2);
    }
    if (tid < TB*6) mlsh[tid] = g_mult[b0*6 + tid];
    // B fragments -> smem
    {
        const float4* src = (const float4*)g_Bf;
        float4* dst = (float4*)Bmem;
        #pragma unroll
        for (int i = tid; i < 864; i += BT) dst[i] = src[i];
    }
    __syncthreads();

    for (int i = tid; i < TB*72; i += BT) {
        int s = i / 72, c = i - s*72;
        int g = c / 12;
        int xcls = (g == 0 || g == 5) ? g : (5 - g);
        Asl[i] = scx[c] * mlsh[s*6 + xcls];
    }
    __syncthreads();

    // A build: thread = row (s*36 + m); pads m=0,35 are zero rows.
    // bank swizzle: XOR bits[2:4) of in-block idx with (rowin>>1)&3
    {
        const int row = tid;
        const int s = row / 36;
        const int m = row - s*36;
        const bool interior = (m >= 1) && (m <= 34);
        const float* xr = x + (size_t)(b0 + s) * SAMP + (m - 1);
        const float* As = Asl + s*72;
        const int rowin = row & 15;
        const int rpart = (row >> 4)*1152 + (rowin & 7)*16 + (rowin >> 3);
        const int rsw   = ((rowin >> 1) & 3) << 2;
        #pragma unroll 4
        for (int c = 0; c < 72; c++) {
            float hv = 0.f;
            if (interior) hv = fmaxf(fmaf(As[c], xr[c*HH], Bc[c]), 0.f);
            Amem[rpart + (cpart[c] ^ rsw)] = f2tf32(hv);
        }
    }
    __syncthreads();

    // mainloop: warp owns m-tiles 2*wid, 2*wid+1; 108 tf32 MMAs
    float d[2][6][4];
    #pragma unroll
    for (int i = 0; i < 2; i++)
        #pragma unroll
        for (int n = 0; n < 6; n++)
            #pragma unroll
            for (int r = 0; r < 4; r++) d[i][n][r] = 0.f;

    {
        const int mt0 = wid*2, mt1 = wid*2 + 1;
        const int lane_sw = (lane & 28) | ((lane & 3) ^ ((lane >> 3) & 3));
        const uint4* Af = (const uint4*)Amem;
        const uint2* Bf = (const uint2*)Bmem;
        #pragma unroll
        for (int ks = 0; ks < 9; ks++) {
            uint4 a0 = Af[(mt0*9 + ks)*32 + lane_sw];
            uint4 a1 = Af[(mt1*9 + ks)*32 + lane_sw];
            #pragma unroll
            for (int nt = 0; nt < 6; nt++) {
                uint2 b = Bf[(nt*9 + ks)*32 + lane];
                MMAT32(d[0][nt], a0, b.x, b.y);
                MMAT32(d[1][nt], a1, b.x, b.y);
            }
        }
    }
    __syncthreads();   // all A reads done; D overlays A

    // store D to smem: row-major, stride 50
    {
        #pragma unroll
        for (int i = 0; i < 2; i++) {
            const int row0 = (wid*2 + i)*16 + (lane >> 2);
            #pragma unroll
            for (int nt = 0; nt < 6; nt++) {
                const int col = nt*8 + 2*(lane & 3);
                *(float2*)(Dmem + row0*DSTRIDE + col)       = make_float2(d[i][nt][0], d[i][nt][1]);
                *(float2*)(Dmem + (row0 + 8)*DSTRIDE + col) = make_float2(d[i][nt][2], d[i][nt][3]);
            }
        }
    }
    __syncthreads();

    // epilogue: out[h,oc] = D[s36+h, oc] + D[s36+h+1, 16+oc] + D[s36+h+2, 32+oc]
    if (tid < 272) {
        const int s = tid / 34;
        const int h = tid - s*34;
        const float* dr = Dmem + (s*36 + h)*DSTRIDE;
        float* ob = out + (size_t)(b0 + s) * OSAMP + 72*HH + h;
        #pragma unroll
        for (int oc = 0; oc < 12; oc++) {
            float v = dr[oc] + dr[DSTRIDE + 16 + oc] + dr[2*DSTRIDE + 32 + oc];
            ob[oc*HH] = v;
        }
    }
}

// ---------------------------------------------------------------------------
extern "C" void kernel_launch(void* const* d_in, const int* in_sizes, int n_in,
                              void* d_out, int out_size)
{
    const float* x      = (const float*)d_in[0];
    const float* gamma  = (const float*)d_in[1];
    const float* beta   = (const float*)d_in[2];
    const float* conv_w = (const float*)d_in[3];
    const float* fc_w   = (const float*)d_in[4];
    const float* fc_b   = (const float*)d_in[5];
    float* out = (float*)d_out;

    const int B = in_sizes[0] / SAMP;   // 16384

    cudaFuncSetAttribute(k3_mma, cudaFuncAttributeMaxDynamicSharedMemorySize, SMEM_K3);

    k1_stats<<<B, 128>>>(x, fc_w, fc_b, out);
    k2_reduce<<<RED_BLOCKS, 144>>>();
    k2b_final<<<1, 72>>>(gamma, beta);
    k2c_wb<<<14, 256>>>(conv_w);
    k3_mma<<<B / TB, BT, SMEM_K3>>>(x, out);
}

// round 11
// speedup vs baseline: 2.2317x; 1.4459x over previous
#include <cuda_runtime.h>
#include <cuda_bf16.h>
#include <math.h>
#include <cstdint>

#define BATCH   16384
#define CCH     72
#define HH      34
#define SAMP    2448
#define OSAMP   2856
#define TB      8             /* samples per conv block */
#define BT      288           /* conv block threads (9 warps, 18 m16-tiles) */
#define RED_BLOCKS 64
#define RED_PER    256
#define BN_COUNT   (16384.0f*34.0f)
#define BN_EPS_F   1e-5f

/* k3 smem layout (bytes) */
#define OFF_ASL 0             /* 576 f  */
#define OFF_BC  2304          /* 72 f   */
#define OFF_SCX 2592          /* 72 f   */
#define OFF_XC  2880          /* 72 i   */
#define OFF_ML  3168          /* 48 f   */
#define OFF_A   3584          /* 18*9*128 u32 = 82944 B */
#define OFF_B   86528         /* 3456 u32 = 13824 B */
#define SMEM_K3 100352
#define OFF_D   OFF_A         /* D overlays A: 288 x 50 f */
#define DSTRIDE 50

__device__ float g_mult[BATCH*6];
__device__ float g_part[BATCH*144];
__device__ float g_part2[RED_BLOCKS*144];
__device__ float g_ss[144];
__device__ unsigned int g_Bf[3456];   /* tf32 B fragments */

__device__ __forceinline__ float sigmoidf_(float z) {
    return 1.0f / (1.0f + __expf(-z));
}
__device__ __forceinline__ unsigned int f2tf32(float v) {
    unsigned int u;
    asm("cvt.rna.tf32.f32 %0, %1;" : "=r"(u) : "f"(v));
    return u;
}

#define MMAT32(d, a, bx, by) \
    asm volatile("mma.sync.aligned.m16n8k8.row.col.f32.tf32.tf32.f32 " \
        "{%0,%1,%2,%3}, {%4,%5,%6,%7}, {%8,%9}, {%0,%1,%2,%3};" \
        : "+f"((d)[0]), "+f"((d)[1]), "+f"((d)[2]), "+f"((d)[3]) \
        : "r"((a).x), "r"((a).y), "r"((a).z), "r"((a).w), "r"(bx), "r"(by))

// ---------------------------------------------------------------------------
// K1: per-sample gates + BN partial sums + copy x into output channels [0,72)
// ---------------------------------------------------------------------------
__global__ void __launch_bounds__(128) k1_stats(
    const float* __restrict__ x, const float* __restrict__ fcw,
    const float* __restrict__ fcb, float* __restrict__ out)
{
    __shared__ float xs[SAMP];
    __shared__ float ws[HH];
    __shared__ float s1[CCH], s2[CCH], sw[CCH];
    __shared__ float lin[6];

    const int b = blockIdx.x, tid = threadIdx.x;
    const float4* xin4 = (const float4*)(x + (size_t)b * SAMP);
    float4* out4 = (float4*)(out + (size_t)b * OSAMP);
    float4* xs4 = (float4*)xs;
    #pragma unroll
    for (int i = tid; i < SAMP/4; i += 128) { float4 v = xin4[i]; xs4[i] = v; out4[i] = v; }
    if (tid < HH) ws[tid] = fcw[tid];
    __syncthreads();

    if (tid < CCH) {
        float a1 = 0.f, a2 = 0.f, aw = 0.f;
        const float* row = xs + tid * HH;
        #pragma unroll
        for (int h = 0; h < HH; h++) { float v = row[h]; a1 += v; a2 += v*v; aw += v*ws[h]; }
        s1[tid] = a1; s2[tid] = a2; sw[tid] = aw;
    }
    __syncthreads();
    if (tid < 6) {
        float s = 0.f;
        #pragma unroll
        for (int c = 0; c < 12; c++) s += sw[tid*12 + c];
        lin[tid] = s * (1.0f/12.0f) + fcb[0];
    }
    __syncthreads();
    if (tid < CCH) {
        const int cls = tid / 12;
        float mult;
        if (cls == 0)      mult = sigmoidf_(lin[5] + lin[0]);
        else if (cls == 5) mult = 1.0f;
        else               mult = sigmoidf_(lin[5-cls] + lin[5]);
        int src = (cls == 0 || cls == 5) ? tid : tid + 12*(5 - 2*cls);
        g_part[(size_t)b*144 + tid*2 + 0] = mult * s1[src];
        g_part[(size_t)b*144 + tid*2 + 1] = mult * mult * s2[src];
        if ((tid % 12) == 0) g_mult[b*6 + cls] = mult;
    }
}

__global__ void __launch_bounds__(144) k2_reduce()
{
    const int t = threadIdx.x, blk = blockIdx.x;
    float acc = 0.f;
    size_t base = (size_t)blk * RED_PER * 144 + t;
    #pragma unroll 8
    for (int i = 0; i < RED_PER; i++) acc += g_part[base + (size_t)i * 144];
    g_part2[blk*144 + t] = acc;
}

__global__ void __launch_bounds__(72) k2b_final(
    const float* __restrict__ gamma, const float* __restrict__ beta)
{
    const int c = threadIdx.x;
    float s = 0.f, q = 0.f;
    #pragma unroll 8
    for (int i = 0; i < RED_BLOCKS; i++) {
        s += g_part2[i*144 + 2*c + 0];
        q += g_part2[i*144 + 2*c + 1];
    }
    const float inv = 1.0f / BN_COUNT;
    float mu = s*inv, var = q*inv - mu*mu;
    float scale = gamma[c] * rsqrtf(var + BN_EPS_F);
    g_ss[c] = scale;
    g_ss[72+c] = beta[c] - mu*scale;
}

// ---------------------------------------------------------------------------
// K2c: build tf32 B fragments in mma.m16n8k8 col-major layout (parallel).
// ---------------------------------------------------------------------------
__global__ void __launch_bounds__(256) k2c_wb(const float* __restrict__ convw)
{
    int idx = blockIdx.x * 256 + threadIdx.x;
    if (idx >= 3456) return;
    int r  = idx & 1;
    int l  = (idx >> 1) & 31;
    int q  = idx >> 6;
    int ks = q % 9;
    int nt = q / 9;
    int n    = nt*8 + (l >> 2);
    int tap  = n >> 4;
    int oc   = n & 15;
    int chan = ks*8 + (l & 3) + 4*r;
    unsigned int val = 0u;
    if (oc < 12) val = f2tf32(convw[oc*216 + chan*3 + tap]);
    g_Bf[idx] = val;
}

// ---------------------------------------------------------------------------
// K3: BN/relu -> tf32 A fragments in smem -> mma.sync GEMM -> tap epilogue
// A-build uses 24-wide register batches to expose MLP=24 on the x loads.
// ---------------------------------------------------------------------------
__global__ void __launch_bounds__(BT, 2) k3_mma(
    const float* __restrict__ x, float* __restrict__ out)
{
    extern __shared__ char smem[];
    float*        Asl  = (float*)(smem + OFF_ASL);
    float*        Bc   = (float*)(smem + OFF_BC);
    float*        scx  = (float*)(smem + OFF_SCX);
    int*          cpart= (int*)  (smem + OFF_XC);
    float*        mlsh = (float*)(smem + OFF_ML);
    unsigned int* Amem = (unsigned int*)(smem + OFF_A);
    unsigned int* Bmem = (unsigned int*)(smem + OFF_B);
    float*        Dmem = (float*)(smem + OFF_D);

    const int tid  = threadIdx.x;
    const int wid  = tid >> 5;
    const int lane = tid & 31;
    const int b0   = blockIdx.x * TB;

    // tables
    if (tid < 72) {
        int g = tid/12, r = tid - g*12;
        int xcls = (g == 0 || g == 5) ? g : (5 - g);
        int xc = 12*xcls + r;
        scx[tid] = g_ss[xc];
        Bc[tid]  = g_ss[72 + xc];
        cpart[tid] = (xc >> 3)*128 + (xc & 3)*4 + 2*((xc & 7) >> 2);
    }
    if (tid < TB*6) mlsh[tid] = g_mult[b0*6 + tid];
    // B fragments -> smem
    {
        const float4* src = (const float4*)g_Bf;
        float4* dst = (float4*)Bmem;
        #pragma unroll
        for (int i = tid; i < 864; i += BT) dst[i] = src[i];
    }
    __syncthreads();

    for (int i = tid; i < TB*72; i += BT) {
        int s = i / 72, c = i - s*72;
        int g = c / 12;
        int xcls = (g == 0 || g == 5) ? g : (5 - g);
        Asl[i] = scx[c] * mlsh[s*6 + xcls];
    }
    __syncthreads();

    // A build: thread = row (s*36 + m); pads m=0,35 are zero rows.
    // 3 batches x 24 registers: front-batched LDGs (MLP=24), then transform+STS.
    {
        const int row = tid;
        const int s = row / 36;
        const int m = row - s*36;
        const bool interior = (m >= 1) && (m <= 34);
        const float* xr = x + (size_t)(b0 + s) * SAMP + (m - 1);
        const float* As = Asl + s*72;
        const int rowin = row & 15;
        const int rpart = (row >> 4)*1152 + (rowin & 7)*16 + (rowin >> 3);
        const int rsw   = ((rowin >> 1) & 3) << 2;
        #pragma unroll
        for (int bch = 0; bch < 3; bch++) {
            float v[24];
            #pragma unroll
            for (int j = 0; j < 24; j++)
                v[j] = interior ? xr[(bch*24 + j)*HH] : 0.f;
            #pragma unroll
            for (int j = 0; j < 24; j++) {
                const int c = bch*24 + j;
                float hv = fmaxf(fmaf(As[c], v[j], Bc[c]), 0.f);
                Amem[rpart + (cpart[c] ^ rsw)] = f2tf32(hv);
            }
        }
    }
    __syncthreads();

    // mainloop: warp owns m-tiles 2*wid, 2*wid+1; 108 tf32 MMAs
    float d[2][6][4];
    #pragma unroll
    for (int i = 0; i < 2; i++)
        #pragma unroll
        for (int n = 0; n < 6; n++)
            #pragma unroll
            for (int r = 0; r < 4; r++) d[i][n][r] = 0.f;

    {
        const int mt0 = wid*2, mt1 = wid*2 + 1;
        const int lane_sw = (lane & 28) | ((lane & 3) ^ ((lane >> 3) & 3));
        const uint4* Af = (const uint4*)Amem;
        const uint2* Bf = (const uint2*)Bmem;
        #pragma unroll
        for (int ks = 0; ks < 9; ks++) {
            uint4 a0 = Af[(mt0*9 + ks)*32 + lane_sw];
            uint4 a1 = Af[(mt1*9 + ks)*32 + lane_sw];
            #pragma unroll
            for (int nt = 0; nt < 6; nt++) {
                uint2 b = Bf[(nt*9 + ks)*32 + lane];
                MMAT32(d[0][nt], a0, b.x, b.y);
                MMAT32(d[1][nt], a1, b.x, b.y);
            }
        }
    }
    __syncthreads();   // all A reads done; D overlays A

    // store D to smem: row-major, stride 50
    {
        #pragma unroll
        for (int i = 0; i < 2; i++) {
            const int row0 = (wid*2 + i)*16 + (lane >> 2);
            #pragma unroll
            for (int nt = 0; nt < 6; nt++) {
                const int col = nt*8 + 2*(lane & 3);
                *(float2*)(Dmem + row0*DSTRIDE + col)       = make_float2(d[i][nt][0], d[i][nt][1]);
                *(float2*)(Dmem + (row0 + 8)*DSTRIDE + col) = make_float2(d[i][nt][2], d[i][nt][3]);
            }
        }
    }
    __syncthreads();

    // epilogue: out[h,oc] = D[s36+h, oc] + D[s36+h+1, 16+oc] + D[s36+h+2, 32+oc]
    if (tid < 272) {
        const int s = tid / 34;
        const int h = tid - s*34;
        const float* dr = Dmem + (s*36 + h)*DSTRIDE;
        float* ob = out + (size_t)(b0 + s) * OSAMP + 72*HH + h;
        #pragma unroll
        for (int oc = 0; oc < 12; oc++) {
            float v = dr[oc] + dr[DSTRIDE + 16 + oc] + dr[2*DSTRIDE + 32 + oc];
            ob[oc*HH] = v;
        }
    }
}

// ---------------------------------------------------------------------------
extern "C" void kernel_launch(void* const* d_in, const int* in_sizes, int n_in,
                              void* d_out, int out_size)
{
    const float* x      = (const float*)d_in[0];
    const float* gamma  = (const float*)d_in[1];
    const float* beta   = (const float*)d_in[2];
    const float* conv_w = (const float*)d_in[3];
    const float* fc_w   = (const float*)d_in[4];
    const float* fc_b   = (const float*)d_in[5];
    float* out = (float*)d_out;

    const int B = in_sizes[0] / SAMP;   // 16384

    cudaFuncSetAttribute(k3_mma, cudaFuncAttributeMaxDynamicSharedMemorySize, SMEM_K3);

    k1_stats<<<B, 128>>>(x, fc_w, fc_b, out);
    k2_reduce<<<RED_BLOCKS, 144>>>();
    k2b_final<<<1, 72>>>(gamma, beta);
    k2c_wb<<<14, 256>>>(conv_w);
    k3_mma<<<B / TB, BT, SMEM_K3>>>(x, out);
}